// round 3
// baseline (speedup 1.0000x reference)
#include <cuda_runtime.h>
#include <cstddef>
#include <cstdint>

// ChamferLossSelf: B=4, N=4096, D=3.
// loss[b] = sum_j min_i ||g_i-p_j||^2 + sum_i min_j ||g_i-p_j||^2
//         + sum_k (sort(selfNN(g))[k] - sort(selfNN(p))[k])^2
//
// min_r ||q-r||^2 = |q|^2 + min_r (|r|^2 - 2 q.r)
// Inner loop packs 2 refs per fma.rn.f32x2 (FFMA2) and runs 2 queries/thread:
// per 4 distances: 2x LDS.128 + 6 FFMA2 (fma pipe) + 4 FMNMX (alu pipe).

constexpr int N_PTS = 4096;
constexpr int B_MAX = 4;
constexpr int QB    = 256;              // threads per block
constexpr int QPT   = 2;                // queries per thread
constexpr int QBLK  = QB * QPT;         // 512 queries per block
constexpr int NCHNK = N_PTS / QBLK;     // 8 chunks
constexpr int TILE  = 1024;             // refs staged per tile
constexpr int PAIRS = TILE / 2;
constexpr float BIG = 3.4e38f;

typedef unsigned long long ull;

__device__ float g_selfmin[2][B_MAX][N_PTS];
__device__ float g_partial[2][B_MAX][NCHNK];

__device__ __forceinline__ ull pack2(float a, float b) {
    ull r;
    asm("mov.b64 %0, {%1, %2};" : "=l"(r) : "f"(a), "f"(b));
    return r;
}
__device__ __forceinline__ void unpack2(ull v, float& a, float& b) {
    asm("mov.b64 {%0, %1}, %2;" : "=f"(a), "=f"(b) : "l"(v));
}
__device__ __forceinline__ ull ffma2(ull a, ull b, ull c) {
    ull d;
    asm("fma.rn.f32x2 %0, %1, %2, %3;" : "=l"(d) : "l"(a), "l"(b), "l"(c));
    return d;
}

// ---------------------------------------------------------------------------
// K1: all 4 NN passes in one launch.
// unit = blockIdx.x : chunk = u&7, pass = (u>>3)&3, b = u>>5
// pass 0: q=gts  r=preds ; pass 1: q=preds r=gts ; pass 2: gts self ; pass 3: preds self
// ---------------------------------------------------------------------------
__global__ void __launch_bounds__(QB) nn_all_kernel(const float* __restrict__ gts,
                                                    const float* __restrict__ preds) {
    const int u     = blockIdx.x;
    const int chunk = u & (NCHNK - 1);
    const int pass  = (u >> 3) & 3;
    const int b     = u >> 5;

    const float* q;
    const float* r;
    if (pass == 0)      { q = gts;   r = preds; }
    else if (pass == 1) { q = preds; r = gts;   }
    else if (pass == 2) { q = gts;   r = gts;   }
    else                { q = preds; r = preds; }
    q += (size_t)b * N_PTS * 3;
    r += (size_t)b * N_PTS * 3;
    const bool self = (pass >= 2);

    const int qiA = chunk * QBLK + threadIdx.x;         // [c*512, c*512+256)
    const int qiB = qiA + QB;                           // [c*512+256, c*512+512)

    const float qAx = q[qiA * 3], qAy = q[qiA * 3 + 1], qAz = q[qiA * 3 + 2];
    const float qBx = q[qiB * 3], qBy = q[qiB * 3 + 1], qBz = q[qiB * 3 + 2];
    const float qqA = fmaf(qAx, qAx, fmaf(qAy, qAy, qAz * qAz));
    const float qqB = fmaf(qBx, qBx, fmaf(qBy, qBy, qBz * qBz));

    const ull nxA = pack2(-2.0f * qAx, -2.0f * qAx);
    const ull nyA = pack2(-2.0f * qAy, -2.0f * qAy);
    const ull nzA = pack2(-2.0f * qAz, -2.0f * qAz);
    const ull nxB = pack2(-2.0f * qBx, -2.0f * qBx);
    const ull nyB = pack2(-2.0f * qBy, -2.0f * qBy);
    const ull nzB = pack2(-2.0f * qBz, -2.0f * qBz);

    // Pair-of-refs layout: sXY[p] = (x_2p, x_2p+1, y_2p, y_2p+1), sZW likewise (w = |r|^2).
    __shared__ float sXY[PAIRS * 4];
    __shared__ float sZW[PAIRS * 4];

    float bA0 = BIG, bA1 = BIG, bB0 = BIG, bB1 = BIG;
    // Tile holding this block's diagonal refs (both queries fall in the same 1024-tile).
    const int diag_tile = (chunk * QBLK) & ~(TILE - 1);

    for (int t0 = 0; t0 < N_PTS; t0 += TILE) {
        __syncthreads();
#pragma unroll
        for (int t = threadIdx.x; t < TILE; t += QB) {
            const float* rp = r + (size_t)(t0 + t) * 3;
            const float rx = rp[0], ry = rp[1], rz = rp[2];
            const float rw = fmaf(rx, rx, fmaf(ry, ry, rz * rz));
            const int p = t >> 1, l = t & 1;
            sXY[p * 4 + l]     = rx;
            sXY[p * 4 + 2 + l] = ry;
            sZW[p * 4 + l]     = rz;
            sZW[p * 4 + 2 + l] = rw;
        }
        __syncthreads();

        const ulonglong2* __restrict__ pXY = (const ulonglong2*)sXY;
        const ulonglong2* __restrict__ pZW = (const ulonglong2*)sZW;

        if (self && t0 == diag_tile) {
            const int relA = qiA - t0;      // 0..1023
            const int relB = qiB - t0;
#pragma unroll 4
            for (int p = 0; p < PAIRS; ++p) {
                const ulonglong2 xy = pXY[p];
                const ulonglong2 zw = pZW[p];
                const ull dA = ffma2(nxA, xy.x, ffma2(nyA, xy.y, ffma2(nzA, zw.x, zw.y)));
                const ull dB = ffma2(nxB, xy.x, ffma2(nyB, xy.y, ffma2(nzB, zw.x, zw.y)));
                float a0, a1, c0, c1;
                unpack2(dA, a0, a1);
                unpack2(dB, c0, c1);
                const int r0 = 2 * p, r1 = 2 * p + 1;
                if (r0 == relA) a0 = BIG;
                if (r1 == relA) a1 = BIG;
                if (r0 == relB) c0 = BIG;
                if (r1 == relB) c1 = BIG;
                bA0 = fminf(bA0, a0); bA1 = fminf(bA1, a1);
                bB0 = fminf(bB0, c0); bB1 = fminf(bB1, c1);
            }
        } else {
#pragma unroll 8
            for (int p = 0; p < PAIRS; ++p) {
                const ulonglong2 xy = pXY[p];
                const ulonglong2 zw = pZW[p];
                const ull dA = ffma2(nxA, xy.x, ffma2(nyA, xy.y, ffma2(nzA, zw.x, zw.y)));
                const ull dB = ffma2(nxB, xy.x, ffma2(nyB, xy.y, ffma2(nzB, zw.x, zw.y)));
                float a0, a1, c0, c1;
                unpack2(dA, a0, a1);
                unpack2(dB, c0, c1);
                bA0 = fminf(bA0, a0); bA1 = fminf(bA1, a1);
                bB0 = fminf(bB0, c0); bB1 = fminf(bB1, c1);
            }
        }
    }

    const float valA = fminf(bA0, bA1) + qqA;
    const float valB = fminf(bB0, bB1) + qqB;

    if (self) {
        g_selfmin[pass - 2][b][qiA] = valA;
        g_selfmin[pass - 2][b][qiB] = valB;
    } else {
        // block sum reduction (deterministic)
        float v = valA + valB;
        __shared__ float red[QB / 32];
#pragma unroll
        for (int o = 16; o; o >>= 1) v += __shfl_xor_sync(0xffffffffu, v, o);
        if ((threadIdx.x & 31) == 0) red[threadIdx.x >> 5] = v;
        __syncthreads();
        if (threadIdx.x == 0) {
            float s = 0.0f;
#pragma unroll
            for (int w = 0; w < QB / 32; ++w) s += red[w];
            g_partial[pass][b][chunk] = s;
        }
    }
}

// ---------------------------------------------------------------------------
// Hybrid bitonic sort of 4096 floats in smem by a 256-thread group.
// t = group-local thread id (0..255). Groups run in lockstep (shared barriers).
// ---------------------------------------------------------------------------
__device__ __forceinline__ void bitonic_sort_4096(float* s, const int t) {
    float v[16];
#pragma unroll
    for (int w = 0; w < 16; ++w) v[w] = s[w * 256 + t];
#pragma unroll
    for (int k = 2; k <= 32; k <<= 1) {
#pragma unroll
        for (int j = k >> 1; j >= 1; j >>= 1) {
#pragma unroll
            for (int w = 0; w < 16; ++w) {
                const int i = w * 256 + t;
                const float pv = __shfl_xor_sync(0xffffffffu, v[w], j);
                const bool up    = ((i & k) == 0);
                const bool lower = ((t & j) == 0);
                v[w] = (lower == up) ? fminf(v[w], pv) : fmaxf(v[w], pv);
            }
        }
    }
#pragma unroll
    for (int w = 0; w < 16; ++w) s[w * 256 + t] = v[w];

    for (int k = 64; k <= 4096; k <<= 1) {
        for (int j = k >> 1; j >= 32; j >>= 1) {
            __syncthreads();
#pragma unroll
            for (int w = 0; w < 16; ++w) {
                const int i = w * 256 + t;
                if ((i & j) == 0) {
                    const int ix = i | j;
                    const float a = s[i], c = s[ix];
                    const bool up = ((i & k) == 0);
                    if ((a > c) == up) { s[i] = c; s[ix] = a; }
                }
            }
        }
        __syncthreads();
#pragma unroll
        for (int w = 0; w < 16; ++w) v[w] = s[w * 256 + t];
#pragma unroll
        for (int j = 16; j >= 1; j >>= 1) {
#pragma unroll
            for (int w = 0; w < 16; ++w) {
                const int i = w * 256 + t;
                const float pv = __shfl_xor_sync(0xffffffffu, v[w], j);
                const bool up    = ((i & k) == 0);
                const bool lower = ((t & j) == 0);
                v[w] = (lower == up) ? fminf(v[w], pv) : fmaxf(v[w], pv);
            }
        }
#pragma unroll
        for (int w = 0; w < 16; ++w) s[w * 256 + t] = v[w];
    }
    __syncthreads();
}

// ---------------------------------------------------------------------------
// K2: one block per batch, 512 threads. Group 0 sorts the gts self-NN array,
// group 1 sorts the preds array (lockstep barriers), then fused ordering +
// cross-partial reduction -> out[b].
// ---------------------------------------------------------------------------
__global__ void __launch_bounds__(512) finalize_kernel(float* __restrict__ out) {
    const int b   = blockIdx.x;
    const int tid = threadIdx.x;
    const int g   = tid >> 8;        // which array this thread's group sorts
    const int t   = tid & 255;       // group-local id

    __shared__ float s[2][N_PTS];

    for (int i = t; i < N_PTS; i += 256) s[g][i] = g_selfmin[g][b][i];
    __syncthreads();
    bitonic_sort_4096(s[g], t);

    float acc = 0.0f;
    for (int i = tid; i < N_PTS; i += 512) {
        const float d = s[0][i] - s[1][i];
        acc = fmaf(d, d, acc);
    }
    if (tid < 2 * NCHNK)
        acc += g_partial[tid >> 3][b][tid & (NCHNK - 1)];

    __shared__ float red[16];
#pragma unroll
    for (int o = 16; o; o >>= 1) acc += __shfl_xor_sync(0xffffffffu, acc, o);
    if ((tid & 31) == 0) red[tid >> 5] = acc;
    __syncthreads();
    if (tid == 0) {
        float sum = 0.0f;
#pragma unroll
        for (int w = 0; w < 16; ++w) sum += red[w];
        out[b] = sum;
    }
}

extern "C" void kernel_launch(void* const* d_in, const int* in_sizes, int n_in,
                              void* d_out, int out_size) {
    const float* gts   = (const float*)d_in[0];
    const float* preds = (const float*)d_in[1];
    float* out = (float*)d_out;
    const int B = in_sizes[0] / (N_PTS * 3);

    nn_all_kernel<<<B * 4 * NCHNK, QB>>>(gts, preds);
    finalize_kernel<<<B, 512>>>(out);
}

// round 4
// speedup vs baseline: 1.4736x; 1.4736x over previous
#include <cuda_runtime.h>
#include <cstddef>

// ChamferLossSelf: B=4, N=4096, D=3.
// min_r ||q-r||^2 = |q|^2 + min_r (|r|^2 - 2 q.r); packed fma.rn.f32x2 inner loop.

constexpr int N_PTS = 4096;
constexpr int B_MAX = 4;
constexpr int THR   = 1024;             // threads per block (all kernels)
constexpr int QPT   = 2;                // queries per thread
constexpr int QBLK  = THR * QPT;        // 2048 queries per NN block
constexpr int NCHNK = N_PTS / QBLK;     // 2 query chunks
constexpr int S     = 8;                // ref slices
constexpr int SLICE = N_PTS / S;        // 512 refs per slice (single stage, no tile loop)
constexpr int SPAIR = SLICE / 2;        // 256 packed ref pairs
constexpr float BIG = 3.4e38f;

typedef unsigned long long ull;

__device__ float g_selfpart [2][B_MAX][S][N_PTS];   // per-slice self-NN partial mins
__device__ float g_crosspart[2][B_MAX][S][N_PTS];   // per-slice cross-NN partial mins
__device__ float g_sorted   [2][B_MAX][N_PTS];      // sorted self-NN dists

__device__ __forceinline__ ull pack2(float a, float b) {
    ull r; asm("mov.b64 %0, {%1, %2};" : "=l"(r) : "f"(a), "f"(b)); return r;
}
__device__ __forceinline__ void unpack2(ull v, float& a, float& b) {
    asm("mov.b64 {%0, %1}, %2;" : "=f"(a), "=f"(b) : "l"(v));
}
__device__ __forceinline__ ull ffma2(ull a, ull b, ull c) {
    ull d; asm("fma.rn.f32x2 %0, %1, %2, %3;" : "=l"(d) : "l"(a), "l"(b), "l"(c)); return d;
}

// ---------------------------------------------------------------------------
// Core: 2048 queries (2/thread) vs one 512-ref slice. Stages refs as packed
// pairs in smem; inner loop = 2 LDS.128 + 6 FFMA2 + 4 FMNMX per 4 distances.
// ---------------------------------------------------------------------------
template <bool MASKED>
__device__ __forceinline__ void nn_slice(const float* __restrict__ q,
                                         const float* __restrict__ r,
                                         int qiA, int qiB, int rbase,
                                         float* sXY, float* sZW,
                                         float& outA, float& outB) {
    const int tid = threadIdx.x;

    const float qAx = q[qiA * 3], qAy = q[qiA * 3 + 1], qAz = q[qiA * 3 + 2];
    const float qBx = q[qiB * 3], qBy = q[qiB * 3 + 1], qBz = q[qiB * 3 + 2];
    const float qqA = fmaf(qAx, qAx, fmaf(qAy, qAy, qAz * qAz));
    const float qqB = fmaf(qBx, qBx, fmaf(qBy, qBy, qBz * qBz));

    const ull nxA = pack2(-2.0f * qAx, -2.0f * qAx);
    const ull nyA = pack2(-2.0f * qAy, -2.0f * qAy);
    const ull nzA = pack2(-2.0f * qAz, -2.0f * qAz);
    const ull nxB = pack2(-2.0f * qBx, -2.0f * qBx);
    const ull nyB = pack2(-2.0f * qBy, -2.0f * qBy);
    const ull nzB = pack2(-2.0f * qBz, -2.0f * qBz);

    // Stage slice: pair layout sXY[p] = (x0,x1,y0,y1), sZW[p] = (z0,z1,w0,w1), w=|r|^2
    for (int t = tid; t < SLICE; t += THR) {
        const float* rp = r + (size_t)(rbase + t) * 3;
        const float rx = rp[0], ry = rp[1], rz = rp[2];
        const float rw = fmaf(rx, rx, fmaf(ry, ry, rz * rz));
        const int p = t >> 1, l = t & 1;
        sXY[p * 4 + l]     = rx;
        sXY[p * 4 + 2 + l] = ry;
        sZW[p * 4 + l]     = rz;
        sZW[p * 4 + 2 + l] = rw;
    }
    __syncthreads();

    // Diagonal targets (self passes): which pair index / lane to mask.
    int mA0 = -1, mA1 = -1, mB0 = -1, mB1 = -1;
    if (MASKED) {
        const int relA = qiA - rbase, relB = qiB - rbase;
        if (relA >= 0 && relA < SLICE) { if (relA & 1) mA1 = relA >> 1; else mA0 = relA >> 1; }
        if (relB >= 0 && relB < SLICE) { if (relB & 1) mB1 = relB >> 1; else mB0 = relB >> 1; }
    }

    const ulonglong2* __restrict__ pXY = (const ulonglong2*)sXY;
    const ulonglong2* __restrict__ pZW = (const ulonglong2*)sZW;

    float bA0 = BIG, bA1 = BIG, bB0 = BIG, bB1 = BIG;
#pragma unroll 8
    for (int p = 0; p < SPAIR; ++p) {
        const ulonglong2 xy = pXY[p];
        const ulonglong2 zw = pZW[p];
        const ull dA = ffma2(nxA, xy.x, ffma2(nyA, xy.y, ffma2(nzA, zw.x, zw.y)));
        const ull dB = ffma2(nxB, xy.x, ffma2(nyB, xy.y, ffma2(nzB, zw.x, zw.y)));
        float a0, a1, c0, c1;
        unpack2(dA, a0, a1);
        unpack2(dB, c0, c1);
        if (MASKED) {
            if (p == mA0) a0 = BIG;
            if (p == mA1) a1 = BIG;
            if (p == mB0) c0 = BIG;
            if (p == mB1) c1 = BIG;
        }
        bA0 = fminf(bA0, a0); bA1 = fminf(bA1, a1);
        bB0 = fminf(bB0, c0); bB1 = fminf(bB1, c1);
    }
    outA = fminf(bA0, bA1) + qqA;
    outB = fminf(bB0, bB1) + qqB;
}

// ---------------------------------------------------------------------------
// K1: self-NN partial mins. grid = 2 * B * NCHNK * S (=128 for B=4).
// ---------------------------------------------------------------------------
__global__ void __launch_bounds__(THR) self_nn_kernel(const float* __restrict__ gts,
                                                      const float* __restrict__ preds,
                                                      int B) {
    __shared__ __align__(16) float sXY[SPAIR * 4];
    __shared__ __align__(16) float sZW[SPAIR * 4];

    int u = blockIdx.x;
    const int s     = u % S;        u /= S;
    const int chunk = u % NCHNK;    u /= NCHNK;
    const int b     = u % B;        u /= B;
    const int pass  = u;            // 0: gts self, 1: preds self

    const float* p = (pass == 0 ? gts : preds) + (size_t)b * N_PTS * 3;
    const int qiA = chunk * QBLK + threadIdx.x;
    const int qiB = qiA + THR;
    const int rbase = s * SLICE;
    const bool overlap = (rbase >= chunk * QBLK) && (rbase < chunk * QBLK + QBLK);

    float vA, vB;
    if (overlap) nn_slice<true >(p, p, qiA, qiB, rbase, sXY, sZW, vA, vB);
    else         nn_slice<false>(p, p, qiA, qiB, rbase, sXY, sZW, vA, vB);

    g_selfpart[pass][b][s][qiA] = vA;
    g_selfpart[pass][b][s][qiB] = vB;
}

// ---------------------------------------------------------------------------
// Bitonic sort of 4096 floats in smem, 1024 threads, 4 elems/thread.
// Strides >=32 via smem, strides <=16 via warp shuffles.
// ---------------------------------------------------------------------------
__device__ __forceinline__ void bitonic_sort_4096(float* s) {
    const int t = threadIdx.x;
    float v[4];
#pragma unroll
    for (int w = 0; w < 4; ++w) v[w] = s[w * 1024 + t];
#pragma unroll
    for (int k = 2; k <= 32; k <<= 1) {
#pragma unroll
        for (int j = k >> 1; j >= 1; j >>= 1) {
#pragma unroll
            for (int w = 0; w < 4; ++w) {
                const int i = w * 1024 + t;
                const float pv = __shfl_xor_sync(0xffffffffu, v[w], j);
                const bool up    = ((i & k) == 0);
                const bool lower = ((t & j) == 0);
                v[w] = (lower == up) ? fminf(v[w], pv) : fmaxf(v[w], pv);
            }
        }
    }
#pragma unroll
    for (int w = 0; w < 4; ++w) s[w * 1024 + t] = v[w];

    for (int k = 64; k <= 4096; k <<= 1) {
        for (int j = k >> 1; j >= 32; j >>= 1) {
            __syncthreads();
#pragma unroll
            for (int w = 0; w < 4; ++w) {
                const int i = w * 1024 + t;
                if ((i & j) == 0) {
                    const int ix = i | j;
                    const float a = s[i], c = s[ix];
                    const bool up = ((i & k) == 0);
                    if ((a > c) == up) { s[i] = c; s[ix] = a; }
                }
            }
        }
        __syncthreads();
#pragma unroll
        for (int w = 0; w < 4; ++w) v[w] = s[w * 1024 + t];
#pragma unroll
        for (int j = 16; j >= 1; j >>= 1) {
#pragma unroll
            for (int w = 0; w < 4; ++w) {
                const int i = w * 1024 + t;
                const float pv = __shfl_xor_sync(0xffffffffu, v[w], j);
                const bool up    = ((i & k) == 0);
                const bool lower = ((t & j) == 0);
                v[w] = (lower == up) ? fminf(v[w], pv) : fmaxf(v[w], pv);
            }
        }
#pragma unroll
        for (int w = 0; w < 4; ++w) s[w * 1024 + t] = v[w];
    }
    __syncthreads();
}

// ---------------------------------------------------------------------------
// K2 (fused): blocks [0, 2B) sort one self array each (min-combine slices,
// sort, store); blocks [2B, 2B + 2*B*NCHNK*S) do cross-NN slices.
// ---------------------------------------------------------------------------
__global__ void __launch_bounds__(THR) fused_kernel(const float* __restrict__ gts,
                                                    const float* __restrict__ preds,
                                                    int B) {
    __shared__ __align__(16) float pool[N_PTS];   // 16 KB, shared by both roles

    if ((int)blockIdx.x < 2 * B) {
        const int arr = blockIdx.x & 1;
        const int b   = blockIdx.x >> 1;
        for (int i = threadIdx.x; i < N_PTS; i += THR) {
            float m = g_selfpart[arr][b][0][i];
#pragma unroll
            for (int sp = 1; sp < S; ++sp) m = fminf(m, g_selfpart[arr][b][sp][i]);
            pool[i] = m;
        }
        __syncthreads();
        bitonic_sort_4096(pool);
        for (int i = threadIdx.x; i < N_PTS; i += THR) g_sorted[arr][b][i] = pool[i];
        return;
    }

    int u = blockIdx.x - 2 * B;
    const int s     = u % S;        u /= S;
    const int chunk = u % NCHNK;    u /= NCHNK;
    const int b     = u % B;        u /= B;
    const int pass  = u;            // 0: q=gts r=preds, 1: q=preds r=gts

    const float* q = (pass == 0 ? gts : preds) + (size_t)b * N_PTS * 3;
    const float* r = (pass == 0 ? preds : gts) + (size_t)b * N_PTS * 3;
    const int qiA = chunk * QBLK + threadIdx.x;
    const int qiB = qiA + THR;

    float vA, vB;
    nn_slice<false>(q, r, qiA, qiB, s * SLICE, pool, pool + SPAIR * 4, vA, vB);

    g_crosspart[pass][b][s][qiA] = vA;
    g_crosspart[pass][b][s][qiB] = vB;
}

// ---------------------------------------------------------------------------
// K3: per-batch combine. min over slices of cross partials, sum, + ordering.
// ---------------------------------------------------------------------------
__global__ void __launch_bounds__(THR) combine_kernel(float* __restrict__ out) {
    const int b   = blockIdx.x;
    const int tid = threadIdx.x;

    float acc = 0.0f;
    for (int i = tid; i < N_PTS; i += THR) {
        float m0 = g_crosspart[0][b][0][i];
        float m1 = g_crosspart[1][b][0][i];
#pragma unroll
        for (int sp = 1; sp < S; ++sp) {
            m0 = fminf(m0, g_crosspart[0][b][sp][i]);
            m1 = fminf(m1, g_crosspart[1][b][sp][i]);
        }
        const float d = g_sorted[0][b][i] - g_sorted[1][b][i];
        acc += m0 + m1;
        acc = fmaf(d, d, acc);
    }

    __shared__ float red[32];
#pragma unroll
    for (int o = 16; o; o >>= 1) acc += __shfl_xor_sync(0xffffffffu, acc, o);
    if ((tid & 31) == 0) red[tid >> 5] = acc;
    __syncthreads();
    if (tid == 0) {
        float sum = 0.0f;
#pragma unroll
        for (int w = 0; w < 32; ++w) sum += red[w];
        out[b] = sum;
    }
}

extern "C" void kernel_launch(void* const* d_in, const int* in_sizes, int n_in,
                              void* d_out, int out_size) {
    const float* gts   = (const float*)d_in[0];
    const float* preds = (const float*)d_in[1];
    float* out = (float*)d_out;
    const int B = in_sizes[0] / (N_PTS * 3);

    self_nn_kernel<<<2 * B * NCHNK * S, THR>>>(gts, preds, B);          // 128 blocks
    fused_kernel<<<2 * B + 2 * B * NCHNK * S, THR>>>(gts, preds, B);    // 136 blocks
    combine_kernel<<<B, THR>>>(out);
}

// round 5
// speedup vs baseline: 1.5159x; 1.0287x over previous
#include <cuda_runtime.h>
#include <cstddef>

// ChamferLossSelf: B=4, N=4096, D=3.
// min_r ||q-r||^2 = |q|^2 + min_r (|r|^2 - 2 q.r)
// Inner loop: one asm block per (ref-pair x query) = 3 FFMA2 + 2 FMNMX,
// pack/unpack movs coalesced by ptxas (internal .b64 reg pair).

constexpr int N_PTS = 4096;
constexpr int B_MAX = 4;
constexpr int THR   = 1024;             // threads per block (all kernels)
constexpr int QPT   = 2;                // queries per thread
constexpr int QBLK  = THR * QPT;        // 2048 queries per NN block
constexpr int NCHNK = N_PTS / QBLK;     // 2 query chunks
constexpr int S     = 8;                // ref slices
constexpr int SLICE = N_PTS / S;        // 512 refs per slice
constexpr int SPAIR = SLICE / 2;        // 256 packed ref pairs
constexpr float BIG = 3.4e38f;

typedef unsigned long long ull;

__device__ float g_selfpart [2][B_MAX][S][N_PTS];   // per-slice self-NN partial mins
__device__ float g_crosspart[2][B_MAX][S][N_PTS];   // per-slice cross-NN partial mins
__device__ float g_sorted   [2][B_MAX][N_PTS];      // sorted self-NN dists

__device__ __forceinline__ ull pack2(float a, float b) {
    ull r; asm("mov.b64 %0, {%1, %2};" : "=l"(r) : "f"(a), "f"(b)); return r;
}
__device__ __forceinline__ void unpack2(ull v, float& a, float& b) {
    asm("mov.b64 {%0, %1}, %2;" : "=f"(a), "=f"(b) : "l"(v));
}
__device__ __forceinline__ ull ffma2(ull a, ull b, ull c) {
    ull d; asm("fma.rn.f32x2 %0, %1, %2, %3;" : "=l"(d) : "l"(a), "l"(b), "l"(c)); return d;
}

// d = nx*x2 + ny*y2 + nz*z2 + w2 (packed over a ref pair), then
// b0 = min(b0, d.lo), b1 = min(b1, d.hi). Single asm block so the
// b64->2xf32 split is a register-pair aliasing, not a MOV.
__device__ __forceinline__ void fma2_min(float& b0, float& b1,
                                         ull nx, ull ny, ull nz,
                                         ull x2, ull y2, ull z2, ull w2) {
    asm("{\n\t"
        ".reg .b64 t;\n\t"
        ".reg .f32 lo, hi;\n\t"
        "fma.rn.f32x2 t, %4, %7, %8;\n\t"
        "fma.rn.f32x2 t, %3, %6, t;\n\t"
        "fma.rn.f32x2 t, %2, %5, t;\n\t"
        "mov.b64 {lo, hi}, t;\n\t"
        "min.f32 %0, %0, lo;\n\t"
        "min.f32 %1, %1, hi;\n\t"
        "}"
        : "+f"(b0), "+f"(b1)
        : "l"(nx), "l"(ny), "l"(nz), "l"(x2), "l"(y2), "l"(z2), "l"(w2));
}

// ---------------------------------------------------------------------------
// Core: 2048 queries (2/thread) vs one 512-ref slice staged as packed pairs.
// ---------------------------------------------------------------------------
template <bool MASKED>
__device__ __forceinline__ void nn_slice(const float* __restrict__ q,
                                         const float* __restrict__ r,
                                         int qiA, int qiB, int rbase,
                                         float* sXY, float* sZW,
                                         float& outA, float& outB) {
    const int tid = threadIdx.x;

    const float qAx = q[qiA * 3], qAy = q[qiA * 3 + 1], qAz = q[qiA * 3 + 2];
    const float qBx = q[qiB * 3], qBy = q[qiB * 3 + 1], qBz = q[qiB * 3 + 2];
    const float qqA = fmaf(qAx, qAx, fmaf(qAy, qAy, qAz * qAz));
    const float qqB = fmaf(qBx, qBx, fmaf(qBy, qBy, qBz * qBz));

    const ull nxA = pack2(-2.0f * qAx, -2.0f * qAx);
    const ull nyA = pack2(-2.0f * qAy, -2.0f * qAy);
    const ull nzA = pack2(-2.0f * qAz, -2.0f * qAz);
    const ull nxB = pack2(-2.0f * qBx, -2.0f * qBx);
    const ull nyB = pack2(-2.0f * qBy, -2.0f * qBy);
    const ull nzB = pack2(-2.0f * qBz, -2.0f * qBz);

    // Pair layout: sXY[p] = (x0,x1,y0,y1), sZW[p] = (z0,z1,w0,w1), w=|r|^2
    for (int t = tid; t < SLICE; t += THR) {
        const float* rp = r + (size_t)(rbase + t) * 3;
        const float rx = rp[0], ry = rp[1], rz = rp[2];
        const float rw = fmaf(rx, rx, fmaf(ry, ry, rz * rz));
        const int p = t >> 1, l = t & 1;
        sXY[p * 4 + l]     = rx;
        sXY[p * 4 + 2 + l] = ry;
        sZW[p * 4 + l]     = rz;
        sZW[p * 4 + 2 + l] = rw;
    }
    __syncthreads();

    const ulonglong2* __restrict__ pXY = (const ulonglong2*)sXY;
    const ulonglong2* __restrict__ pZW = (const ulonglong2*)sZW;

    float bA0 = BIG, bA1 = BIG, bB0 = BIG, bB1 = BIG;

    if (MASKED) {
        // Diagonal targets: pair index / lane to force to BIG.
        int mA0 = -1, mA1 = -1, mB0 = -1, mB1 = -1;
        const int relA = qiA - rbase, relB = qiB - rbase;
        if (relA >= 0 && relA < SLICE) { if (relA & 1) mA1 = relA >> 1; else mA0 = relA >> 1; }
        if (relB >= 0 && relB < SLICE) { if (relB & 1) mB1 = relB >> 1; else mB0 = relB >> 1; }
#pragma unroll 4
        for (int p = 0; p < SPAIR; ++p) {
            const ulonglong2 xy = pXY[p];
            const ulonglong2 zw = pZW[p];
            const ull dA = ffma2(nxA, xy.x, ffma2(nyA, xy.y, ffma2(nzA, zw.x, zw.y)));
            const ull dB = ffma2(nxB, xy.x, ffma2(nyB, xy.y, ffma2(nzB, zw.x, zw.y)));
            float a0, a1, c0, c1;
            unpack2(dA, a0, a1);
            unpack2(dB, c0, c1);
            if (p == mA0) a0 = BIG;
            if (p == mA1) a1 = BIG;
            if (p == mB0) c0 = BIG;
            if (p == mB1) c1 = BIG;
            bA0 = fminf(bA0, a0); bA1 = fminf(bA1, a1);
            bB0 = fminf(bB0, c0); bB1 = fminf(bB1, c1);
        }
    } else {
#pragma unroll 8
        for (int p = 0; p < SPAIR; ++p) {
            const ulonglong2 xy = pXY[p];
            const ulonglong2 zw = pZW[p];
            fma2_min(bA0, bA1, nxA, nyA, nzA, xy.x, xy.y, zw.x, zw.y);
            fma2_min(bB0, bB1, nxB, nyB, nzB, xy.x, xy.y, zw.x, zw.y);
        }
    }
    outA = fminf(bA0, bA1) + qqA;
    outB = fminf(bB0, bB1) + qqB;
}

// ---------------------------------------------------------------------------
// K1: self-NN partial mins. grid = 2 * B * NCHNK * S (=128 for B=4).
// ---------------------------------------------------------------------------
__global__ void __launch_bounds__(THR) self_nn_kernel(const float* __restrict__ gts,
                                                      const float* __restrict__ preds,
                                                      int B) {
    __shared__ __align__(16) float sXY[SPAIR * 4];
    __shared__ __align__(16) float sZW[SPAIR * 4];

    int u = blockIdx.x;
    const int s     = u % S;        u /= S;
    const int chunk = u % NCHNK;    u /= NCHNK;
    const int b     = u % B;        u /= B;
    const int pass  = u;            // 0: gts self, 1: preds self

    const float* p = (pass == 0 ? gts : preds) + (size_t)b * N_PTS * 3;
    const int qiA = chunk * QBLK + threadIdx.x;
    const int qiB = qiA + THR;
    const int rbase = s * SLICE;
    const bool overlap = (rbase >= chunk * QBLK) && (rbase < chunk * QBLK + QBLK);

    float vA, vB;
    if (overlap) nn_slice<true >(p, p, qiA, qiB, rbase, sXY, sZW, vA, vB);
    else         nn_slice<false>(p, p, qiA, qiB, rbase, sXY, sZW, vA, vB);

    g_selfpart[pass][b][s][qiA] = vA;
    g_selfpart[pass][b][s][qiB] = vB;
}

// ---------------------------------------------------------------------------
// Bitonic sort of 4096 floats in smem, 1024 threads, 4 elems/thread.
// Strides >=32 via smem, strides <=16 via warp shuffles.
// ---------------------------------------------------------------------------
__device__ __forceinline__ void bitonic_sort_4096(float* s) {
    const int t = threadIdx.x;
    float v[4];
#pragma unroll
    for (int w = 0; w < 4; ++w) v[w] = s[w * 1024 + t];
#pragma unroll
    for (int k = 2; k <= 32; k <<= 1) {
#pragma unroll
        for (int j = k >> 1; j >= 1; j >>= 1) {
#pragma unroll
            for (int w = 0; w < 4; ++w) {
                const int i = w * 1024 + t;
                const float pv = __shfl_xor_sync(0xffffffffu, v[w], j);
                const bool up    = ((i & k) == 0);
                const bool lower = ((t & j) == 0);
                v[w] = (lower == up) ? fminf(v[w], pv) : fmaxf(v[w], pv);
            }
        }
    }
#pragma unroll
    for (int w = 0; w < 4; ++w) s[w * 1024 + t] = v[w];

    for (int k = 64; k <= 4096; k <<= 1) {
        for (int j = k >> 1; j >= 32; j >>= 1) {
            __syncthreads();
#pragma unroll
            for (int w = 0; w < 4; ++w) {
                const int i = w * 1024 + t;
                if ((i & j) == 0) {
                    const int ix = i | j;
                    const float a = s[i], c = s[ix];
                    const bool up = ((i & k) == 0);
                    if ((a > c) == up) { s[i] = c; s[ix] = a; }
                }
            }
        }
        __syncthreads();
#pragma unroll
        for (int w = 0; w < 4; ++w) v[w] = s[w * 1024 + t];
#pragma unroll
        for (int j = 16; j >= 1; j >>= 1) {
#pragma unroll
            for (int w = 0; w < 4; ++w) {
                const int i = w * 1024 + t;
                const float pv = __shfl_xor_sync(0xffffffffu, v[w], j);
                const bool up    = ((i & k) == 0);
                const bool lower = ((t & j) == 0);
                v[w] = (lower == up) ? fminf(v[w], pv) : fmaxf(v[w], pv);
            }
        }
#pragma unroll
        for (int w = 0; w < 4; ++w) s[w * 1024 + t] = v[w];
    }
    __syncthreads();
}

// ---------------------------------------------------------------------------
// K2 (fused): blocks [0, 2B) sort one self array each (min-combine slices,
// sort, store); blocks [2B, ...) do cross-NN slices.
// ---------------------------------------------------------------------------
__global__ void __launch_bounds__(THR) fused_kernel(const float* __restrict__ gts,
                                                    const float* __restrict__ preds,
                                                    int B) {
    __shared__ __align__(16) float pool[N_PTS];   // 16 KB, shared by both roles

    if ((int)blockIdx.x < 2 * B) {
        const int arr = blockIdx.x & 1;
        const int b   = blockIdx.x >> 1;
        for (int i = threadIdx.x; i < N_PTS; i += THR) {
            float m = g_selfpart[arr][b][0][i];
#pragma unroll
            for (int sp = 1; sp < S; ++sp) m = fminf(m, g_selfpart[arr][b][sp][i]);
            pool[i] = m;
        }
        __syncthreads();
        bitonic_sort_4096(pool);
        for (int i = threadIdx.x; i < N_PTS; i += THR) g_sorted[arr][b][i] = pool[i];
        return;
    }

    int u = blockIdx.x - 2 * B;
    const int s     = u % S;        u /= S;
    const int chunk = u % NCHNK;    u /= NCHNK;
    const int b     = u % B;        u /= B;
    const int pass  = u;            // 0: q=gts r=preds, 1: q=preds r=gts

    const float* q = (pass == 0 ? gts : preds) + (size_t)b * N_PTS * 3;
    const float* r = (pass == 0 ? preds : gts) + (size_t)b * N_PTS * 3;
    const int qiA = chunk * QBLK + threadIdx.x;
    const int qiB = qiA + THR;

    float vA, vB;
    nn_slice<false>(q, r, qiA, qiB, s * SLICE, pool, pool + SPAIR * 4, vA, vB);

    g_crosspart[pass][b][s][qiA] = vA;
    g_crosspart[pass][b][s][qiB] = vB;
}

// ---------------------------------------------------------------------------
// K3: per-batch combine. min over slices of cross partials, sum, + ordering.
// ---------------------------------------------------------------------------
__global__ void __launch_bounds__(THR) combine_kernel(float* __restrict__ out) {
    const int b   = blockIdx.x;
    const int tid = threadIdx.x;

    float acc = 0.0f;
    for (int i = tid; i < N_PTS; i += THR) {
        float m0 = g_crosspart[0][b][0][i];
        float m1 = g_crosspart[1][b][0][i];
#pragma unroll
        for (int sp = 1; sp < S; ++sp) {
            m0 = fminf(m0, g_crosspart[0][b][sp][i]);
            m1 = fminf(m1, g_crosspart[1][b][sp][i]);
        }
        const float d = g_sorted[0][b][i] - g_sorted[1][b][i];
        acc += m0 + m1;
        acc = fmaf(d, d, acc);
    }

    __shared__ float red[32];
#pragma unroll
    for (int o = 16; o; o >>= 1) acc += __shfl_xor_sync(0xffffffffu, acc, o);
    if ((tid & 31) == 0) red[tid >> 5] = acc;
    __syncthreads();
    if (tid == 0) {
        float sum = 0.0f;
#pragma unroll
        for (int w = 0; w < 32; ++w) sum += red[w];
        out[b] = sum;
    }
}

extern "C" void kernel_launch(void* const* d_in, const int* in_sizes, int n_in,
                              void* d_out, int out_size) {
    const float* gts   = (const float*)d_in[0];
    const float* preds = (const float*)d_in[1];
    float* out = (float*)d_out;
    const int B = in_sizes[0] / (N_PTS * 3);

    self_nn_kernel<<<2 * B * NCHNK * S, THR>>>(gts, preds, B);          // 128 blocks
    fused_kernel<<<2 * B + 2 * B * NCHNK * S, THR>>>(gts, preds, B);    // 136 blocks
    combine_kernel<<<B, THR>>>(out);
}

// round 6
// speedup vs baseline: 1.5824x; 1.0439x over previous
#include <cuda_runtime.h>
#include <cstddef>

// ChamferLossSelf: B=4, N=4096, D=3.
// min_r ||q-r||^2 = |q|^2 + min_r (|r|^2 - 2 q.r); packed fma.rn.f32x2 inner loop.
// 512-thr blocks, 2 co-resident/SM; diagonal masking confined to one 16-pair
// group per warp (diag ref index == tid for overlap blocks).

constexpr int N_PTS = 4096;
constexpr int B_MAX = 4;
constexpr int THR   = 512;              // threads per block
constexpr int QPT   = 2;                // queries per thread
constexpr int QBLK  = THR * QPT;        // 1024 queries per NN block
constexpr int NCHNK = N_PTS / QBLK;     // 4 query chunks
constexpr int S     = 8;                // ref slices
constexpr int SLICE = N_PTS / S;        // 512 refs per slice
constexpr int SPAIR = SLICE / 2;        // 256 packed ref pairs
constexpr int GRP   = 16;               // pairs per mask-group
constexpr int NGRP  = SPAIR / GRP;      // 16 groups (== warps per block)
constexpr float BIG = 3.4e38f;

typedef unsigned long long ull;

__device__ float g_selfpart [2][B_MAX][S][N_PTS];
__device__ float g_crosspart[2][B_MAX][S][N_PTS];
__device__ float g_sorted   [2][B_MAX][N_PTS];

__device__ __forceinline__ ull pack2(float a, float b) {
    ull r; asm("mov.b64 %0, {%1, %2};" : "=l"(r) : "f"(a), "f"(b)); return r;
}
__device__ __forceinline__ void unpack2(ull v, float& a, float& b) {
    asm("mov.b64 {%0, %1}, %2;" : "=f"(a), "=f"(b) : "l"(v));
}
__device__ __forceinline__ ull ffma2(ull a, ull b, ull c) {
    ull d; asm("fma.rn.f32x2 %0, %1, %2, %3;" : "=l"(d) : "l"(a), "l"(b), "l"(c)); return d;
}
__device__ __forceinline__ void fma2_min(float& b0, float& b1,
                                         ull nx, ull ny, ull nz,
                                         ull x2, ull y2, ull z2, ull w2) {
    asm("{\n\t"
        ".reg .b64 t;\n\t"
        ".reg .f32 lo, hi;\n\t"
        "fma.rn.f32x2 t, %4, %7, %8;\n\t"
        "fma.rn.f32x2 t, %3, %6, t;\n\t"
        "fma.rn.f32x2 t, %2, %5, t;\n\t"
        "mov.b64 {lo, hi}, t;\n\t"
        "min.f32 %0, %0, lo;\n\t"
        "min.f32 %1, %1, hi;\n\t"
        "}"
        : "+f"(b0), "+f"(b1)
        : "l"(nx), "l"(ny), "l"(nz), "l"(x2), "l"(y2), "l"(z2), "l"(w2));
}

struct QPack { ull nx, ny, nz; float qq; };

__device__ __forceinline__ QPack load_q(const float* __restrict__ q, int qi) {
    QPack o;
    const float x = q[qi * 3], y = q[qi * 3 + 1], z = q[qi * 3 + 2];
    o.qq = fmaf(x, x, fmaf(y, y, z * z));
    o.nx = pack2(-2.0f * x, -2.0f * x);
    o.ny = pack2(-2.0f * y, -2.0f * y);
    o.nz = pack2(-2.0f * z, -2.0f * z);
    return o;
}

// Stage slice refs as pairs: sXY[p]=(x0,x1,y0,y1), sZW[p]=(z0,z1,w0,w1), w=|r|^2.
__device__ __forceinline__ void stage_slice(const float* __restrict__ r, int rbase,
                                            float* sXY, float* sZW) {
    const int t = threadIdx.x;            // THR == SLICE: one ref per thread
    const float* rp = r + (size_t)(rbase + t) * 3;
    const float rx = rp[0], ry = rp[1], rz = rp[2];
    const float rw = fmaf(rx, rx, fmaf(ry, ry, rz * rz));
    const int p = t >> 1, l = t & 1;
    sXY[p * 4 + l]     = rx;
    sXY[p * 4 + 2 + l] = ry;
    sZW[p * 4 + l]     = rz;
    sZW[p * 4 + 2 + l] = rw;
}

// ---------------------------------------------------------------------------
// K1: self-NN partial mins. grid = 2*B*NCHNK*S (=256 for B=4).
// ---------------------------------------------------------------------------
__global__ void __launch_bounds__(THR, 2) self_nn_kernel(const float* __restrict__ gts,
                                                         const float* __restrict__ preds,
                                                         int B) {
    __shared__ __align__(16) float sXY[SPAIR * 4];
    __shared__ __align__(16) float sZW[SPAIR * 4];

    int u = blockIdx.x;
    const int s     = u % S;        u /= S;
    const int chunk = u % NCHNK;    u /= NCHNK;
    const int b     = u % B;        u /= B;
    const int pass  = u;            // 0: gts self, 1: preds self

    const float* p = (pass == 0 ? gts : preds) + (size_t)b * N_PTS * 3;
    const int tid = threadIdx.x;
    const int qiA = chunk * QBLK + tid;
    const int qiB = qiA + THR;
    const int rbase = s * SLICE;

    const QPack A = load_q(p, qiA);
    const QPack Bq = load_q(p, qiB);
    stage_slice(p, rbase, sXY, sZW);
    __syncthreads();

    const ulonglong2* __restrict__ pXY = (const ulonglong2*)sXY;
    const ulonglong2* __restrict__ pZW = (const ulonglong2*)sZW;

    float bA0 = BIG, bA1 = BIG, bB0 = BIG, bB1 = BIG;

    const bool overlap = (rbase >= chunk * QBLK) && (rbase < chunk * QBLK + QBLK);

    if (!overlap) {
#pragma unroll 8
        for (int q = 0; q < SPAIR; ++q) {
            const ulonglong2 xy = pXY[q];
            const ulonglong2 zw = pZW[q];
            fma2_min(bA0, bA1, A.nx,  A.ny,  A.nz,  xy.x, xy.y, zw.x, zw.y);
            fma2_min(bB0, bB1, Bq.nx, Bq.ny, Bq.nz, xy.x, xy.y, zw.x, zw.y);
        }
    } else {
        // Diagonal ref index within slice == tid. Masked query: A if this
        // slice is the first half of the chunk, else B (uniform per block).
        const bool maskA = (rbase == chunk * QBLK);
        const int dpair = tid >> 1;
        const int pm0 = (tid & 1) ? -1 : dpair;   // pair idx masking lane 0
        const int pm1 = (tid & 1) ? dpair : -1;   // pair idx masking lane 1
        const int gd = tid >> 5;                  // group containing diag (== warp id)

        for (int g = 0; g < NGRP; ++g) {
            const int base = g * GRP;
            if (g != gd) {
#pragma unroll
                for (int k = 0; k < GRP; ++k) {
                    const ulonglong2 xy = pXY[base + k];
                    const ulonglong2 zw = pZW[base + k];
                    fma2_min(bA0, bA1, A.nx,  A.ny,  A.nz,  xy.x, xy.y, zw.x, zw.y);
                    fma2_min(bB0, bB1, Bq.nx, Bq.ny, Bq.nz, xy.x, xy.y, zw.x, zw.y);
                }
            } else {
#pragma unroll
                for (int k = 0; k < GRP; ++k) {
                    const int q = base + k;
                    const ulonglong2 xy = pXY[q];
                    const ulonglong2 zw = pZW[q];
                    if (maskA) {
                        const ull dA = ffma2(A.nx, xy.x, ffma2(A.ny, xy.y, ffma2(A.nz, zw.x, zw.y)));
                        float e0, e1;
                        unpack2(dA, e0, e1);
                        if (q == pm0) e0 = BIG;
                        if (q == pm1) e1 = BIG;
                        bA0 = fminf(bA0, e0); bA1 = fminf(bA1, e1);
                        fma2_min(bB0, bB1, Bq.nx, Bq.ny, Bq.nz, xy.x, xy.y, zw.x, zw.y);
                    } else {
                        fma2_min(bA0, bA1, A.nx, A.ny, A.nz, xy.x, xy.y, zw.x, zw.y);
                        const ull dB = ffma2(Bq.nx, xy.x, ffma2(Bq.ny, xy.y, ffma2(Bq.nz, zw.x, zw.y)));
                        float e0, e1;
                        unpack2(dB, e0, e1);
                        if (q == pm0) e0 = BIG;
                        if (q == pm1) e1 = BIG;
                        bB0 = fminf(bB0, e0); bB1 = fminf(bB1, e1);
                    }
                }
            }
        }
    }

    g_selfpart[pass][b][s][qiA] = fminf(bA0, bA1) + A.qq;
    g_selfpart[pass][b][s][qiB] = fminf(bB0, bB1) + Bq.qq;
}

// ---------------------------------------------------------------------------
// Bitonic sort of 4096 floats in smem, 512 threads, 8 elems/thread.
// Strides >=32 via smem, strides <=16 via warp shuffles.
// ---------------------------------------------------------------------------
__device__ __forceinline__ void bitonic_sort_4096(float* s) {
    const int t = threadIdx.x;
    float v[8];
#pragma unroll
    for (int w = 0; w < 8; ++w) v[w] = s[w * 512 + t];
#pragma unroll
    for (int k = 2; k <= 32; k <<= 1) {
#pragma unroll
        for (int j = k >> 1; j >= 1; j >>= 1) {
#pragma unroll
            for (int w = 0; w < 8; ++w) {
                const int i = w * 512 + t;
                const float pv = __shfl_xor_sync(0xffffffffu, v[w], j);
                const bool up    = ((i & k) == 0);
                const bool lower = ((t & j) == 0);
                v[w] = (lower == up) ? fminf(v[w], pv) : fmaxf(v[w], pv);
            }
        }
    }
#pragma unroll
    for (int w = 0; w < 8; ++w) s[w * 512 + t] = v[w];

    for (int k = 64; k <= 4096; k <<= 1) {
        for (int j = k >> 1; j >= 32; j >>= 1) {
            __syncthreads();
#pragma unroll
            for (int w = 0; w < 8; ++w) {
                const int i = w * 512 + t;
                if ((i & j) == 0) {
                    const int ix = i | j;
                    const float a = s[i], c = s[ix];
                    const bool up = ((i & k) == 0);
                    if ((a > c) == up) { s[i] = c; s[ix] = a; }
                }
            }
        }
        __syncthreads();
#pragma unroll
        for (int w = 0; w < 8; ++w) v[w] = s[w * 512 + t];
#pragma unroll
        for (int j = 16; j >= 1; j >>= 1) {
#pragma unroll
            for (int w = 0; w < 8; ++w) {
                const int i = w * 512 + t;
                const float pv = __shfl_xor_sync(0xffffffffu, v[w], j);
                const bool up    = ((i & k) == 0);
                const bool lower = ((t & j) == 0);
                v[w] = (lower == up) ? fminf(v[w], pv) : fmaxf(v[w], pv);
            }
        }
#pragma unroll
        for (int w = 0; w < 8; ++w) s[w * 512 + t] = v[w];
    }
    __syncthreads();
}

// ---------------------------------------------------------------------------
// K2 (fused): blocks [0, 2B) min-combine + sort one self array each;
// blocks [2B, 2B + 2*B*NCHNK*S) do cross-NN slices.
// ---------------------------------------------------------------------------
__global__ void __launch_bounds__(THR, 2) fused_kernel(const float* __restrict__ gts,
                                                       const float* __restrict__ preds,
                                                       int B) {
    __shared__ __align__(16) float pool[N_PTS];   // 16 KB (sort); cross uses first 8 KB

    if ((int)blockIdx.x < 2 * B) {
        const int arr = blockIdx.x & 1;
        const int b   = blockIdx.x >> 1;
        for (int i = threadIdx.x; i < N_PTS; i += THR) {
            float m = g_selfpart[arr][b][0][i];
#pragma unroll
            for (int sp = 1; sp < S; ++sp) m = fminf(m, g_selfpart[arr][b][sp][i]);
            pool[i] = m;
        }
        __syncthreads();
        bitonic_sort_4096(pool);
        for (int i = threadIdx.x; i < N_PTS; i += THR) g_sorted[arr][b][i] = pool[i];
        return;
    }

    int u = blockIdx.x - 2 * B;
    const int s     = u % S;        u /= S;
    const int chunk = u % NCHNK;    u /= NCHNK;
    const int b     = u % B;        u /= B;
    const int pass  = u;            // 0: q=gts r=preds, 1: q=preds r=gts

    const float* q = (pass == 0 ? gts : preds) + (size_t)b * N_PTS * 3;
    const float* r = (pass == 0 ? preds : gts) + (size_t)b * N_PTS * 3;
    const int tid = threadIdx.x;
    const int qiA = chunk * QBLK + tid;
    const int qiB = qiA + THR;

    float* sXY = pool;
    float* sZW = pool + SPAIR * 4;

    const QPack A = load_q(q, qiA);
    const QPack Bq = load_q(q, qiB);
    stage_slice(r, s * SLICE, sXY, sZW);
    __syncthreads();

    const ulonglong2* __restrict__ pXY = (const ulonglong2*)sXY;
    const ulonglong2* __restrict__ pZW = (const ulonglong2*)sZW;

    float bA0 = BIG, bA1 = BIG, bB0 = BIG, bB1 = BIG;
#pragma unroll 8
    for (int p = 0; p < SPAIR; ++p) {
        const ulonglong2 xy = pXY[p];
        const ulonglong2 zw = pZW[p];
        fma2_min(bA0, bA1, A.nx,  A.ny,  A.nz,  xy.x, xy.y, zw.x, zw.y);
        fma2_min(bB0, bB1, Bq.nx, Bq.ny, Bq.nz, xy.x, xy.y, zw.x, zw.y);
    }

    g_crosspart[pass][b][s][qiA] = fminf(bA0, bA1) + A.qq;
    g_crosspart[pass][b][s][qiB] = fminf(bB0, bB1) + Bq.qq;
}

// ---------------------------------------------------------------------------
// K3: per-batch combine. min over slices of cross partials, sum, + ordering.
// ---------------------------------------------------------------------------
__global__ void __launch_bounds__(THR) combine_kernel(float* __restrict__ out) {
    const int b   = blockIdx.x;
    const int tid = threadIdx.x;

    float acc = 0.0f;
    for (int i = tid; i < N_PTS; i += THR) {
        float m0 = g_crosspart[0][b][0][i];
        float m1 = g_crosspart[1][b][0][i];
#pragma unroll
        for (int sp = 1; sp < S; ++sp) {
            m0 = fminf(m0, g_crosspart[0][b][sp][i]);
            m1 = fminf(m1, g_crosspart[1][b][sp][i]);
        }
        const float d = g_sorted[0][b][i] - g_sorted[1][b][i];
        acc += m0 + m1;
        acc = fmaf(d, d, acc);
    }

    __shared__ float red[16];
#pragma unroll
    for (int o = 16; o; o >>= 1) acc += __shfl_xor_sync(0xffffffffu, acc, o);
    if ((tid & 31) == 0) red[tid >> 5] = acc;
    __syncthreads();
    if (tid == 0) {
        float sum = 0.0f;
#pragma unroll
        for (int w = 0; w < 16; ++w) sum += red[w];
        out[b] = sum;
    }
}

extern "C" void kernel_launch(void* const* d_in, const int* in_sizes, int n_in,
                              void* d_out, int out_size) {
    const float* gts   = (const float*)d_in[0];
    const float* preds = (const float*)d_in[1];
    float* out = (float*)d_out;
    const int B = in_sizes[0] / (N_PTS * 3);

    self_nn_kernel<<<2 * B * NCHNK * S, THR>>>(gts, preds, B);          // 256 blocks
    fused_kernel<<<2 * B + 2 * B * NCHNK * S, THR>>>(gts, preds, B);    // 264 blocks
    combine_kernel<<<B, THR>>>(out);
}